// round 10
// baseline (speedup 1.0000x reference)
#include <cuda_runtime.h>
#include <cuda_bf16.h>
#include <mma.h>
#include <math.h>
#include <stdint.h>

using namespace nvcuda;

// ---------------------------------------------------------------------------
// ToolCallingModule: sel MLP + gate in exact fp32 (decision boundaries);
// pg/ri MLPs on wmma/HMMA bf16 with 2-term operand split (3 passes,
// err ~2^-16, values only). tcgen05 is unreachable: harness PTX targets
// sm_103 (no 'a'), so only arch-agnostic mma paths compile.
// ---------------------------------------------------------------------------

#define NTOK_MAX 16384

__device__ int   g_count;
__device__ int   g_active_tok[NTOK_MAX];
__device__ int   g_active_tool[NTOK_MAX];
__device__ float g_h1[NTOK_MAX * 512];
__device__ float g_logits[NTOK_MAX * 128];
__device__ float g_p1[NTOK_MAX * 512];
__device__ float g_tr[NTOK_MAX * 2048];
__device__ float g_r1[NTOK_MAX * 512];

// bf16 split weights, transposed to [N,K] K-contiguous
#define WS_PG1 0
#define WS_PG2 1179648
#define WS_RI1 2228224
#define WS_RI2 4325376
#define WS_TOTAL 5373952
__device__ __nv_bfloat16 g_whi[WS_TOTAL];
__device__ __nv_bfloat16 g_wlo[WS_TOTAL];

__global__ void reset_kernel() { g_count = 0; }

// ======================= weight split + transpose ==========================
// W[K,N] fp32 -> Whi/Wlo [N,K] bf16.  block (32,8), tile 32x32.
__global__ void wsplit_kernel(const float* __restrict__ W,
                              __nv_bfloat16* __restrict__ Whi,
                              __nv_bfloat16* __restrict__ Wlo, int K, int N)
{
    __shared__ float t[32][33];
    const int n0 = blockIdx.x * 32, k0 = blockIdx.y * 32;
    const int tx = threadIdx.x, ty = threadIdx.y;
#pragma unroll
    for (int j = 0; j < 32; j += 8)
        t[ty + j][tx] = W[(size_t)(k0 + ty + j) * N + n0 + tx];
    __syncthreads();
#pragma unroll
    for (int j = 0; j < 32; j += 8) {
        float v = t[tx][ty + j];
        __nv_bfloat16 h = __float2bfloat16_rn(v);
        __nv_bfloat16 l = __float2bfloat16_rn(v - __bfloat162float(h));
        size_t o = (size_t)(n0 + ty + j) * K + k0 + tx;
        Whi[o] = h; Wlo[o] = l;
    }
}

// ======================= wmma GEMM (bf16 split x3) =========================
// C[M,N] = act(A[M,K] @ W[K,N] + bias).  BM=BN=128, BK=64.
// 8 warps, 2(m) x 4(n), warp tile 64x32 -> 4x2 accum frags of 16x16.
// A fp32 split on the fly; W pre-split bf16 [N,K] = col-major B operand.
// AMODE 0: dense A0 rows (stride K). 1: concat(hidden[tok],emb[tool]).
// 2: concat(hidden[tok], A1 row gr (2048)).  M = g_count always.
// TG_LD=80: 160-byte rows keep every wmma fragment pointer 32B-aligned
// (wmma load/store requires 256-bit alignment; 144-byte rows violate it).
#define TG_LD 80
#define TG_TILE_ELEMS (128 * TG_LD)          // 10240 bf16 per tile
#define TG_SMEM (4 * TG_TILE_ELEMS * 2)      // 81920 bytes (Ah,Al,Bh,Bl)

template<int AMODE, bool RELU, bool SCATTER>
__global__ void __launch_bounds__(256, 1)
tgemm_kernel(const float* __restrict__ A0, const float* __restrict__ A1,
             const __nv_bfloat16* __restrict__ Whi,
             const __nv_bfloat16* __restrict__ Wlo,
             const float* __restrict__ bias, float* __restrict__ C,
             int K, int N)
{
    extern __shared__ __align__(32) __nv_bfloat16 smem[];
    __nv_bfloat16* sAh = smem;
    __nv_bfloat16* sAl = smem + TG_TILE_ELEMS;
    __nv_bfloat16* sBh = smem + 2 * TG_TILE_ELEMS;
    __nv_bfloat16* sBl = smem + 3 * TG_TILE_ELEMS;

    const int m_count = g_count;
    const int mb = blockIdx.y * 128;
    if (mb >= m_count) return;
    const int nb = blockIdx.x * 128;

    const int tid = threadIdx.x;
    const int wid = tid >> 5;
    const int wm  = wid & 1;     // m-group (0..1), rows wm*64..
    const int wn  = wid >> 1;    // n-group (0..3), cols wn*32..

    wmma::fragment<wmma::accumulator, 16, 16, 16, float> acc[4][2];
#pragma unroll
    for (int i = 0; i < 4; i++)
#pragma unroll
        for (int j = 0; j < 2; j++)
            wmma::fill_fragment(acc[i][j], 0.0f);

    const int nchunk = K >> 6;
    for (int c = 0; c < nchunk; c++) {
        __syncthreads();   // previous compute done reading smem

        // ---- fill A: 128 rows x 64 fp32 -> bf16 hi/lo ----
#pragma unroll
        for (int i = 0; i < 8; i++) {
            const int idx = tid + i * 256;     // float4 units, 0..2047
            const int row = idx >> 4;          // 0..127
            const int c4  = idx & 15;          // 0..15
            const int gr  = mb + row;
            float4 v = make_float4(0.f, 0.f, 0.f, 0.f);
            if (gr < m_count) {
                const int kg = c * 64 + c4 * 4;
                const float* src;
                if (AMODE == 0) {
                    src = A0 + (size_t)gr * K + kg;
                } else if (kg < 2048) {
                    src = A0 + (size_t)g_active_tok[gr] * 2048 + kg;
                } else if (AMODE == 1) {
                    src = A1 + (size_t)g_active_tool[gr] * 256 + (kg - 2048);
                } else {
                    src = A1 + (size_t)gr * 2048 + (kg - 2048);
                }
                v = *(const float4*)src;
            }
            __nv_bfloat16 hx = __float2bfloat16_rn(v.x);
            __nv_bfloat16 hy = __float2bfloat16_rn(v.y);
            __nv_bfloat16 hz = __float2bfloat16_rn(v.z);
            __nv_bfloat16 hw = __float2bfloat16_rn(v.w);
            __nv_bfloat16 lx = __float2bfloat16_rn(v.x - __bfloat162float(hx));
            __nv_bfloat16 ly = __float2bfloat16_rn(v.y - __bfloat162float(hy));
            __nv_bfloat16 lz = __float2bfloat16_rn(v.z - __bfloat162float(hz));
            __nv_bfloat16 lw = __float2bfloat16_rn(v.w - __bfloat162float(hw));
            __nv_bfloat162 h0 = __nv_bfloat162(hx, hy), h1 = __nv_bfloat162(hz, hw);
            __nv_bfloat162 l0 = __nv_bfloat162(lx, ly), l1 = __nv_bfloat162(lz, lw);
            uint2 uh, ul;
            uh.x = *(uint32_t*)&h0; uh.y = *(uint32_t*)&h1;
            ul.x = *(uint32_t*)&l0; ul.y = *(uint32_t*)&l1;
            const int off = row * TG_LD + c4 * 4;   // byte off 160*row+8*c4, 8B aligned
            *(uint2*)(sAh + off) = uh;
            *(uint2*)(sAl + off) = ul;
        }

        // ---- fill B: 128 n-rows x 64 bf16 (hi/lo) from pre-split [N,K] ----
#pragma unroll
        for (int i = 0; i < 4; i++) {
            const int idx = tid + i * 256;     // int4 units (8 bf16), 0..1023
            const int n   = idx >> 3;          // 0..127
            const int c8  = idx & 7;           // 0..7
            const size_t src = (size_t)(nb + n) * K + c * 64 + c8 * 8;
            int4 vh = *(const int4*)(Whi + src);
            int4 vl = *(const int4*)(Wlo + src);
            const int off = n * TG_LD + c8 * 8; // byte off 160n+16c8, 16B aligned
            *(int4*)(sBh + off) = vh;
            *(int4*)(sBl + off) = vl;
        }

        __syncthreads();

        // ---- compute: 4 k-steps of 16, per warp 4x2 frags, 3 mma each ----
#pragma unroll
        for (int ks = 0; ks < 4; ks++) {
            wmma::fragment<wmma::matrix_a, 16, 16, 16, __nv_bfloat16, wmma::row_major> ah[4], al[4];
            wmma::fragment<wmma::matrix_b, 16, 16, 16, __nv_bfloat16, wmma::col_major> bh[2], bl[2];
#pragma unroll
            for (int i = 0; i < 4; i++) {
                const int ro = (wm * 64 + i * 16) * TG_LD + ks * 16;
                wmma::load_matrix_sync(ah[i], sAh + ro, TG_LD);
                wmma::load_matrix_sync(al[i], sAl + ro, TG_LD);
            }
#pragma unroll
            for (int j = 0; j < 2; j++) {
                const int ro = (wn * 32 + j * 16) * TG_LD + ks * 16;
                wmma::load_matrix_sync(bh[j], sBh + ro, TG_LD);
                wmma::load_matrix_sync(bl[j], sBl + ro, TG_LD);
            }
#pragma unroll
            for (int i = 0; i < 4; i++)
#pragma unroll
                for (int j = 0; j < 2; j++) {
                    wmma::mma_sync(acc[i][j], ah[i], bh[j], acc[i][j]);
                    wmma::mma_sync(acc[i][j], ah[i], bl[j], acc[i][j]);
                    wmma::mma_sync(acc[i][j], al[i], bh[j], acc[i][j]);
                }
        }
    }

    // ---- epilogue: stage accum through smem, then bias/relu/scatter ----
    __syncthreads();
    float* stage = (float*)smem;           // 128x128 f32 = 64KB <= TG_SMEM
    float* wst = stage + wid * 2048;       // each warp: 64x32 region
#pragma unroll
    for (int i = 0; i < 4; i++)
#pragma unroll
        for (int j = 0; j < 2; j++)
            wmma::store_matrix_sync(wst + (i * 16) * 32 + j * 16, acc[i][j],
                                    32, wmma::mem_row_major);
    __syncthreads();

#pragma unroll
    for (int it = 0; it < 16; it++) {
        const int idx = tid + it * 256;    // 0..4095 (128 rows x 32 float4)
        const int r   = idx >> 5;
        const int c4  = idx & 31;
        const int gr  = mb + r;
        if (gr >= m_count) continue;
        const int cc  = c4 * 4;
        // region wid' = (r/64) + (cc/32)*2 ; within: (r%64)*32 + (cc%32)
        const float* sp = stage + (((r >> 6) + ((cc >> 5) << 1)) * 2048)
                        + (r & 63) * 32 + (cc & 31);
        float4 v  = *(const float4*)sp;
        float4 b4 = *(const float4*)(bias + nb + cc);
        v.x += b4.x; v.y += b4.y; v.z += b4.z; v.w += b4.w;
        if (RELU) {
            v.x = fmaxf(v.x, 0.f); v.y = fmaxf(v.y, 0.f);
            v.z = fmaxf(v.z, 0.f); v.w = fmaxf(v.w, 0.f);
        }
        const int crow = SCATTER ? g_active_tok[gr] : gr;
        *(float4*)(C + (size_t)crow * N + nb + cc) = v;
    }
}

// ======================= fp32 SGEMM (sel MLP — exact) ======================
template<int AMODE, bool DYNM, bool RELU, bool SCATTER>
__global__ void __launch_bounds__(256, 2)
gemm_kernel(const float* __restrict__ A0, const float* __restrict__ A1,
            const float* __restrict__ W, const float* __restrict__ bias,
            float* __restrict__ C, int M, int K, int N)
{
    __shared__ float As[2][8][128];
    __shared__ float Ws[2][8][128];

    const int m_count = DYNM ? g_count : M;
    const int mb = blockIdx.y * 128;
    if (mb >= m_count) return;
    const int nb = blockIdx.x * 128;

    const int tid  = threadIdx.x;
    const int arow = tid >> 1;
    const int akc  = (tid & 1) << 2;
    const int wkr  = tid >> 5;
    const int wnc  = (tid & 31) << 2;

    const int  gr = mb + arow;
    const bool rv = (!DYNM) || (gr < m_count);

    const float* pa0;
    const float* pa1 = nullptr;
    if (AMODE == 0) {
        pa0 = A0 + (size_t)(rv ? gr : 0) * (size_t)K;
    } else {
        const int tok = rv ? g_active_tok[gr] : 0;
        pa0 = A0 + (size_t)tok * 2048;
        if (AMODE == 1) {
            const int tool = rv ? g_active_tool[gr] : 0;
            pa1 = A1 + (size_t)tool * 256;
        } else {
            pa1 = A1 + (size_t)(rv ? gr : 0) * 2048;
        }
    }
    const float* pw = W + (size_t)wkr * N + nb + wnc;

    const int tx = tid & 15;
    const int ty = tid >> 4;

    float acc[8][8];
#pragma unroll
    for (int i = 0; i < 8; i++)
#pragma unroll
        for (int j = 0; j < 8; j++) acc[i][j] = 0.f;

    const int nkt = K >> 3;
    float4 a_reg, w_reg;

    if (!rv) a_reg = make_float4(0.f, 0.f, 0.f, 0.f);
    else     a_reg = *(const float4*)(pa0 + akc);
    w_reg = *(const float4*)(pw);

    As[0][akc + 0][arow] = a_reg.x;
    As[0][akc + 1][arow] = a_reg.y;
    As[0][akc + 2][arow] = a_reg.z;
    As[0][akc + 3][arow] = a_reg.w;
    *(float4*)&Ws[0][wkr][wnc] = w_reg;
    __syncthreads();

    int buf = 0;
    for (int kt = 0; kt < nkt; kt++) {
        const bool more = (kt + 1 < nkt);
        if (more) {
            const int gk = (kt + 1) * 8 + akc;
            if (AMODE == 0) {
                a_reg = rv ? *(const float4*)(pa0 + gk) : make_float4(0.f, 0.f, 0.f, 0.f);
            } else {
                if (!rv)            a_reg = make_float4(0.f, 0.f, 0.f, 0.f);
                else if (gk < 2048) a_reg = *(const float4*)(pa0 + gk);
                else                a_reg = *(const float4*)(pa1 + (gk - 2048));
            }
            w_reg = *(const float4*)(pw + (size_t)(kt + 1) * 8 * N);
        }
#pragma unroll
        for (int k = 0; k < 8; k++) {
            float4 a0  = *(const float4*)&As[buf][k][ty * 4];
            float4 a1v = *(const float4*)&As[buf][k][64 + ty * 4];
            float4 b0  = *(const float4*)&Ws[buf][k][tx * 4];
            float4 b1v = *(const float4*)&Ws[buf][k][64 + tx * 4];
            float av[8] = {a0.x, a0.y, a0.z, a0.w, a1v.x, a1v.y, a1v.z, a1v.w};
            float bv[8] = {b0.x, b0.y, b0.z, b0.w, b1v.x, b1v.y, b1v.z, b1v.w};
#pragma unroll
            for (int i = 0; i < 8; i++)
#pragma unroll
                for (int j = 0; j < 8; j++)
                    acc[i][j] += av[i] * bv[j];
        }
        if (more) {
            buf ^= 1;
            As[buf][akc + 0][arow] = a_reg.x;
            As[buf][akc + 1][arow] = a_reg.y;
            As[buf][akc + 2][arow] = a_reg.z;
            As[buf][akc + 3][arow] = a_reg.w;
            *(float4*)&Ws[buf][wkr][wnc] = w_reg;
            __syncthreads();
        }
    }

    float4 bs0 = *(const float4*)(bias + nb + tx * 4);
    float4 bs1 = *(const float4*)(bias + nb + 64 + tx * 4);
    float bcol[8] = {bs0.x, bs0.y, bs0.z, bs0.w, bs1.x, bs1.y, bs1.z, bs1.w};

#pragma unroll
    for (int i = 0; i < 8; i++) {
        const int rl = (i < 4) ? (ty * 4 + i) : (64 + ty * 4 + (i - 4));
        const int r  = mb + rl;
        if (DYNM && r >= m_count) continue;
        const int crow = SCATTER ? g_active_tok[r] : r;
        float* cp = C + (size_t)crow * N + nb;
        float v[8];
#pragma unroll
        for (int j = 0; j < 8; j++) {
            float x = acc[i][j] + bcol[j];
            v[j] = RELU ? fmaxf(x, 0.f) : x;
        }
        *(float4*)(cp + tx * 4)      = make_float4(v[0], v[1], v[2], v[3]);
        *(float4*)(cp + 64 + tx * 4) = make_float4(v[4], v[5], v[6], v[7]);
    }
}

// ======================= select (gate/softmax/top3) ========================
__device__ __forceinline__ float warp_sum(float v) {
#pragma unroll
    for (int s = 16; s > 0; s >>= 1) v += __shfl_xor_sync(0xffffffffu, v, s);
    return v;
}
__device__ __forceinline__ float warp_max(float v) {
#pragma unroll
    for (int s = 16; s > 0; s >>= 1) v = fmaxf(v, __shfl_xor_sync(0xffffffffu, v, s));
    return v;
}
__device__ __forceinline__ unsigned long long warp_maxull(unsigned long long v) {
#pragma unroll
    for (int s = 16; s > 0; s >>= 1) {
        unsigned long long o = __shfl_xor_sync(0xffffffffu, v, s);
        v = (o > v) ? o : v;
    }
    return v;
}

__global__ void select_kernel(const float* __restrict__ hidden,
                              const float* __restrict__ gate_w,
                              const float* __restrict__ gate_b,
                              float* __restrict__ out_enh,
                              float* __restrict__ out_probs,
                              float* __restrict__ out_call)
{
    const int t    = blockIdx.x;
    const int tid  = threadIdx.x;
    const int lane = tid & 31;
    const int wrp  = tid >> 5;

    __shared__ float sredf[4];
    __shared__ unsigned long long sredu[4];
    __shared__ float s_gate;
    __shared__ int   s_top[3];
    __shared__ int   s_active;

    const float* hrow = hidden + (size_t)t * 2048;

    float acc = 0.f;
#pragma unroll
    for (int i = 0; i < 16; i++)
        acc += hrow[tid + i * 128] * gate_w[tid + i * 128];
    acc = warp_sum(acc);
    if (lane == 0) sredf[wrp] = acc;
    __syncthreads();
    if (tid == 0) s_gate = sredf[0] + sredf[1] + sredf[2] + sredf[3] + gate_b[0];
    __syncthreads();
    const bool should = s_gate > 0.f;

    const float lg = g_logits[(size_t)t * 128 + tid];
    float m = warp_max(lg);
    if (lane == 0) sredf[wrp] = m;
    __syncthreads();
    const float mx = fmaxf(fmaxf(sredf[0], sredf[1]), fmaxf(sredf[2], sredf[3]));
    const float e = expf(lg - mx);
    float sm = warp_sum(e);
    __syncthreads();
    if (lane == 0) sredf[wrp] = sm;
    __syncthreads();
    const float denom = sredf[0] + sredf[1] + sredf[2] + sredf[3];
    out_probs[(size_t)t * 128 + tid] = e / denom;

    unsigned fb = __float_as_uint(lg);
    fb = (fb & 0x80000000u) ? ~fb : (fb | 0x80000000u);
    unsigned long long key =
        ((unsigned long long)fb << 32) | (unsigned)(127 - tid);

    for (int kk = 0; kk < 3; kk++) {
        unsigned long long k2 = warp_maxull(key);
        if (lane == 0) sredu[wrp] = k2;
        __syncthreads();
        if (tid == 0) {
            unsigned long long best = sredu[0];
            if (sredu[1] > best) best = sredu[1];
            if (sredu[2] > best) best = sredu[2];
            if (sredu[3] > best) best = sredu[3];
            s_top[kk] = 127 - (int)(best & 0xffffffffu);
        }
        __syncthreads();
        if (tid == s_top[kk]) key = 0;
    }

    if (tid == 0) {
        int last = -1, selt = 0;
#pragma unroll
        for (int kk = 0; kk < 3; kk++) {
            if (should && s_top[kk] < 64) { last = kk; selt = s_top[kk]; }
        }
        out_call[t] = should ? 1.f : 0.f;
        if (last >= 0) {
            const int pos = atomicAdd(&g_count, 1);
            g_active_tok[pos]  = t;
            g_active_tool[pos] = selt;
            s_active = 1;
        } else {
            s_active = 0;
        }
    }
    __syncthreads();

    if (!s_active) {
        const float4* hv = (const float4*)hrow;
        float4* ov = (float4*)(out_enh + (size_t)t * 2048);
#pragma unroll
        for (int i = 0; i < 4; i++)
            ov[tid + i * 128] = hv[tid + i * 128];
    }
}

// ===========================================================================
extern "C" void kernel_launch(void* const* d_in, const int* in_sizes, int n_in,
                              void* d_out, int out_size)
{
    if (n_in < 16) return;
    const float* hidden = (const float*)d_in[0];
    const float* emb    = (const float*)d_in[1];
    const float* gate_w = (const float*)d_in[2];
    const float* gate_b = (const float*)d_in[3];
    const float* sel_w1 = (const float*)d_in[4];
    const float* sel_b1 = (const float*)d_in[5];
    const float* sel_w2 = (const float*)d_in[6];
    const float* sel_b2 = (const float*)d_in[7];
    const float* pg_w1  = (const float*)d_in[8];
    const float* pg_b1  = (const float*)d_in[9];
    const float* pg_w2  = (const float*)d_in[10];
    const float* pg_b2  = (const float*)d_in[11];
    const float* ri_w1  = (const float*)d_in[12];
    const float* ri_b1  = (const float*)d_in[13];
    const float* ri_w2  = (const float*)d_in[14];
    const float* ri_b2  = (const float*)d_in[15];

    const int Ntok = in_sizes[0] / 2048;
    float* out       = (float*)d_out;
    float* out_enh   = out;
    float* out_probs = out + (size_t)Ntok * 2048;
    float* out_call  = out_probs + (size_t)Ntok * 128;

    float *p_h1, *p_logits, *p_p1, *p_tr, *p_r1;
    cudaGetSymbolAddress((void**)&p_h1,     g_h1);
    cudaGetSymbolAddress((void**)&p_logits, g_logits);
    cudaGetSymbolAddress((void**)&p_p1,     g_p1);
    cudaGetSymbolAddress((void**)&p_tr,     g_tr);
    cudaGetSymbolAddress((void**)&p_r1,     g_r1);
    __nv_bfloat16 *p_whi, *p_wlo;
    cudaGetSymbolAddress((void**)&p_whi, g_whi);
    cudaGetSymbolAddress((void**)&p_wlo, g_wlo);

    cudaFuncSetAttribute(tgemm_kernel<1, true,  false>, cudaFuncAttributeMaxDynamicSharedMemorySize, TG_SMEM);
    cudaFuncSetAttribute(tgemm_kernel<0, false, false>, cudaFuncAttributeMaxDynamicSharedMemorySize, TG_SMEM);
    cudaFuncSetAttribute(tgemm_kernel<2, true,  false>, cudaFuncAttributeMaxDynamicSharedMemorySize, TG_SMEM);
    cudaFuncSetAttribute(tgemm_kernel<0, false, true >, cudaFuncAttributeMaxDynamicSharedMemorySize, TG_SMEM);

    const int MB = (Ntok + 127) / 128;

    reset_kernel<<<1, 1>>>();

    // weight split+transpose (bf16 hi/lo, [N,K]) for pg/ri
    wsplit_kernel<<<dim3(512/32, 2304/32), dim3(32,8)>>>(pg_w1, p_whi + WS_PG1, p_wlo + WS_PG1, 2304, 512);
    wsplit_kernel<<<dim3(2048/32, 512/32), dim3(32,8)>>>(pg_w2, p_whi + WS_PG2, p_wlo + WS_PG2, 512, 2048);
    wsplit_kernel<<<dim3(512/32, 4096/32), dim3(32,8)>>>(ri_w1, p_whi + WS_RI1, p_wlo + WS_RI1, 4096, 512);
    wsplit_kernel<<<dim3(2048/32, 512/32), dim3(32,8)>>>(ri_w2, p_whi + WS_RI2, p_wlo + WS_RI2, 512, 2048);

    // selector MLP (all tokens, exact fp32)
    gemm_kernel<0, false, true,  false><<<dim3(4,  MB), 256>>>(hidden, nullptr, sel_w1, sel_b1, p_h1,     Ntok, 2048, 512);
    gemm_kernel<0, false, false, false><<<dim3(1,  MB), 256>>>(p_h1,   nullptr, sel_w2, sel_b2, p_logits, Ntok, 512,  128);

    // gate + softmax + top3 + compaction + passthrough
    select_kernel<<<Ntok, 128>>>(hidden, gate_w, gate_b, out_enh, out_probs, out_call);

    // param generator (active tokens, wmma bf16-split)
    tgemm_kernel<1, true,  false><<<dim3(4,  MB), 256, TG_SMEM>>>(hidden, emb,  p_whi + WS_PG1, p_wlo + WS_PG1, pg_b1, p_p1, 2304, 512);
    tgemm_kernel<0, false, false><<<dim3(16, MB), 256, TG_SMEM>>>(p_p1, nullptr, p_whi + WS_PG2, p_wlo + WS_PG2, pg_b2, p_tr, 512,  2048);

    // result integration (active tokens, scatter into enhanced)
    tgemm_kernel<2, true,  false><<<dim3(4,  MB), 256, TG_SMEM>>>(hidden, p_tr, p_whi + WS_RI1, p_wlo + WS_RI1, ri_b1, p_r1, 4096, 512);
    tgemm_kernel<0, false, true ><<<dim3(16, MB), 256, TG_SMEM>>>(p_r1, nullptr, p_whi + WS_RI2, p_wlo + WS_RI2, ri_b2, out_enh, 512, 2048);
}

// round 13
// speedup vs baseline: 1.4490x; 1.4490x over previous
#include <cuda_runtime.h>
#include <cuda_bf16.h>
#include <mma.h>
#include <math.h>
#include <stdint.h>

using namespace nvcuda;

// ---------------------------------------------------------------------------
// ToolCallingModule: sel MLP + gate exact fp32 (decision boundaries);
// pg/ri MLPs on wmma/HMMA bf16, 2-term split (hh+hl+lh, err ~2^-16).
// R10 lesson: conversion + single-buffer latency dominated the GEMM loop.
// Now ALL activations are pre-split to bf16 hi/lo in global memory and the
// GEMM mainloop is pure cp.async double-buffer -> LDSM -> HMMA.
// ---------------------------------------------------------------------------

#define NTOK_MAX 16384

__device__ int   g_count;
__device__ int   g_active_tok[NTOK_MAX];
__device__ int   g_active_tool[NTOK_MAX];
__device__ float g_h1[NTOK_MAX * 512];
__device__ float g_logits[NTOK_MAX * 128];

// bf16 split weights, transposed to [N,K] K-contiguous
#define WS_PG1 0
#define WS_PG2 1179648
#define WS_RI1 2228224
#define WS_RI2 4325376
#define WS_TOTAL 5373952
__device__ __nv_bfloat16 g_whi[WS_TOTAL];
__device__ __nv_bfloat16 g_wlo[WS_TOTAL];

// bf16 split activations (hi/lo pairs)
__device__ __nv_bfloat16 g_hh[NTOK_MAX * 2048], g_hl[NTOK_MAX * 2048];
__device__ __nv_bfloat16 g_eh[128 * 256],       g_el[128 * 256];
__device__ __nv_bfloat16 g_p1h[NTOK_MAX * 512], g_p1l[NTOK_MAX * 512];
__device__ __nv_bfloat16 g_trh[NTOK_MAX * 2048], g_trl[NTOK_MAX * 2048];
__device__ __nv_bfloat16 g_r1h[NTOK_MAX * 512], g_r1l[NTOK_MAX * 512];

__global__ void reset_kernel() { g_count = 0; }

// ======================= helpers ===========================================
__device__ __forceinline__ void cp_async16(uint32_t dst, const void* src) {
    asm volatile("cp.async.cg.shared.global [%0], [%1], 16;"
                 :: "r"(dst), "l"(src) : "memory");
}
__device__ __forceinline__ void cp_commit() {
    asm volatile("cp.async.commit_group;" ::: "memory");
}
template<int W> __device__ __forceinline__ void cp_wait() {
    asm volatile("cp.async.wait_group %0;" :: "n"(W) : "memory");
}

__device__ __forceinline__ void split2(float x, __nv_bfloat16& h, __nv_bfloat16& l) {
    h = __float2bfloat16_rn(x);
    l = __float2bfloat16_rn(x - __bfloat162float(h));
}

// ======================= weight split + transpose ==========================
__global__ void wsplit_kernel(const float* __restrict__ W,
                              __nv_bfloat16* __restrict__ Whi,
                              __nv_bfloat16* __restrict__ Wlo, int K, int N)
{
    __shared__ float t[32][33];
    const int n0 = blockIdx.x * 32, k0 = blockIdx.y * 32;
    const int tx = threadIdx.x, ty = threadIdx.y;
#pragma unroll
    for (int j = 0; j < 32; j += 8)
        t[ty + j][tx] = W[(size_t)(k0 + ty + j) * N + n0 + tx];
    __syncthreads();
#pragma unroll
    for (int j = 0; j < 32; j += 8) {
        float v = t[tx][ty + j];
        __nv_bfloat16 h, l; split2(v, h, l);
        size_t o = (size_t)(n0 + ty + j) * K + k0 + tx;
        Whi[o] = h; Wlo[o] = l;
    }
}

// ======================= activation split (elementwise) ====================
__global__ void fsplit_kernel(const float* __restrict__ X,
                              __nv_bfloat16* __restrict__ Xh,
                              __nv_bfloat16* __restrict__ Xl, int n4)
{
    const int i = blockIdx.x * blockDim.x + threadIdx.x;
    if (i >= n4) return;
    float4 v = ((const float4*)X)[i];
    __nv_bfloat16 h0,h1,h2,h3,l0,l1,l2,l3;
    split2(v.x,h0,l0); split2(v.y,h1,l1); split2(v.z,h2,l2); split2(v.w,h3,l3);
    __nv_bfloat162 H0(h0,h1), H1(h2,h3), L0(l0,l1), L1(l2,l3);
    uint2 uh, ul;
    uh.x=*(uint32_t*)&H0; uh.y=*(uint32_t*)&H1;
    ul.x=*(uint32_t*)&L0; ul.y=*(uint32_t*)&L1;
    ((uint2*)Xh)[i] = uh;
    ((uint2*)Xl)[i] = ul;
}

// ======================= wmma GEMM (pre-split, cp.async 2-stage) ===========
// C = act(A @ W + bias). BM=BN=128, BK=64, 8 warps (2m x 4n), warp 64x32.
// A/W both pre-split bf16 (hi/lo). AMODE 0: dense Ah0/Al0 rows (stride K).
// 1: concat(hidden[tok] (2048), emb[tool] (256)). 2: concat(hidden[tok], A1 row gr).
// OUTMODE 0: write Ch/Cl bf16 split rows (dense compacted). 1: fp32 scatter.
#define TG_LD 80                              // 160B rows, 32B-aligned frags
#define TG_TILE (128 * TG_LD)                 // elems per tile
#define TG_STAGE (4 * TG_TILE)                // Ah,Al,Bh,Bl
#define TG_SMEM (2 * TG_STAGE * 2)            // 163840 bytes

template<int AMODE, bool RELU, int OUTMODE>
__global__ void __launch_bounds__(256, 1)
tgemm_kernel(const __nv_bfloat16* __restrict__ Ah0, const __nv_bfloat16* __restrict__ Al0,
             const __nv_bfloat16* __restrict__ Ah1, const __nv_bfloat16* __restrict__ Al1,
             const __nv_bfloat16* __restrict__ Whi, const __nv_bfloat16* __restrict__ Wlo,
             const float* __restrict__ bias,
             float* __restrict__ Cf, __nv_bfloat16* __restrict__ Ch,
             __nv_bfloat16* __restrict__ Cl, int K, int N)
{
    extern __shared__ __align__(32) __nv_bfloat16 smem[];
    const int m_count = g_count;
    const int mb = blockIdx.y * 128;
    if (mb >= m_count) return;
    const int nb = blockIdx.x * 128;

    const int tid = threadIdx.x;
    const int wid = tid >> 5;
    const int wm  = wid & 1;
    const int wn  = wid >> 1;
    const uint32_t sbase = (uint32_t)__cvta_generic_to_shared(smem);

    // per-thread copy mapping: idx=tid+i*256 -> (row=idx>>3, c8=idx&7), 4 i's
    const __nv_bfloat16 *a1h[4], *a1l[4], *a2h[4], *a2l[4], *wbh[4], *wbl[4];
    uint32_t soff[4];
    int koff[4];
#pragma unroll
    for (int i = 0; i < 4; i++) {
        const int idx = tid + i * 256;
        const int r = idx >> 3, c8 = idx & 7;
        koff[i] = c8 * 8;
        soff[i] = (uint32_t)(r * TG_LD + c8 * 8) * 2;
        const int gr = mb + r;
        const int rr = (gr < m_count) ? gr : 0;
        if (AMODE == 0) {
            a1h[i] = Ah0 + (size_t)rr * K;  a1l[i] = Al0 + (size_t)rr * K;
            a2h[i] = a1h[i];                a2l[i] = a1l[i];   // unused
        } else {
            const int tok = g_active_tok[rr];
            a1h[i] = Ah0 + (size_t)tok * 2048;  a1l[i] = Al0 + (size_t)tok * 2048;
            if (AMODE == 1) {
                const int tool = g_active_tool[rr];
                a2h[i] = Ah1 + (size_t)tool * 256;  a2l[i] = Al1 + (size_t)tool * 256;
            } else {
                a2h[i] = Ah1 + (size_t)rr * 2048;   a2l[i] = Al1 + (size_t)rr * 2048;
            }
        }
        wbh[i] = Whi + (size_t)(nb + r) * K;  wbl[i] = Wlo + (size_t)(nb + r) * K;
    }

    const int nchunk = K >> 6;
    auto fill = [&](int c, int s) {
        const uint32_t st = sbase + (uint32_t)s * TG_STAGE * 2;
        const uint32_t aH = st, aL = st + TG_TILE * 2;
        const uint32_t bH = st + 2 * TG_TILE * 2, bL = st + 3 * TG_TILE * 2;
        const int kg0 = c * 64;
#pragma unroll
        for (int i = 0; i < 4; i++) {
            const int kg = kg0 + koff[i];
            const __nv_bfloat16 *ph, *pl;
            if (AMODE == 0 || kg < 2048) { ph = a1h[i] + kg;          pl = a1l[i] + kg; }
            else                          { ph = a2h[i] + (kg - 2048); pl = a2l[i] + (kg - 2048); }
            cp_async16(aH + soff[i], ph);
            cp_async16(aL + soff[i], pl);
            cp_async16(bH + soff[i], wbh[i] + kg0 + koff[i]);
            cp_async16(bL + soff[i], wbl[i] + kg0 + koff[i]);
        }
    };

    wmma::fragment<wmma::accumulator, 16, 16, 16, float> acc[4][2];
#pragma unroll
    for (int i = 0; i < 4; i++)
#pragma unroll
        for (int j = 0; j < 2; j++)
            wmma::fill_fragment(acc[i][j], 0.0f);

    fill(0, 0); cp_commit();

    for (int c = 0; c < nchunk; c++) {
        const int s = c & 1;
        if (c + 1 < nchunk) { fill(c + 1, s ^ 1); cp_commit(); cp_wait<1>(); }
        else                { cp_wait<0>(); }
        __syncthreads();

        const __nv_bfloat16* sAh = smem + s * TG_STAGE;
        const __nv_bfloat16* sAl = sAh + TG_TILE;
        const __nv_bfloat16* sBh = sAh + 2 * TG_TILE;
        const __nv_bfloat16* sBl = sAh + 3 * TG_TILE;

#pragma unroll
        for (int ks = 0; ks < 4; ks++) {
            wmma::fragment<wmma::matrix_a, 16, 16, 16, __nv_bfloat16, wmma::row_major> ah[4], al[4];
            wmma::fragment<wmma::matrix_b, 16, 16, 16, __nv_bfloat16, wmma::col_major> bh[2], bl[2];
#pragma unroll
            for (int i = 0; i < 4; i++) {
                const int ro = (wm * 64 + i * 16) * TG_LD + ks * 16;
                wmma::load_matrix_sync(ah[i], sAh + ro, TG_LD);
                wmma::load_matrix_sync(al[i], sAl + ro, TG_LD);
            }
#pragma unroll
            for (int j = 0; j < 2; j++) {
                const int ro = (wn * 32 + j * 16) * TG_LD + ks * 16;
                wmma::load_matrix_sync(bh[j], sBh + ro, TG_LD);
                wmma::load_matrix_sync(bl[j], sBl + ro, TG_LD);
            }
#pragma unroll
            for (int i = 0; i < 4; i++)
#pragma unroll
                for (int j = 0; j < 2; j++) {
                    wmma::mma_sync(acc[i][j], ah[i], bh[j], acc[i][j]);
                    wmma::mma_sync(acc[i][j], ah[i], bl[j], acc[i][j]);
                    wmma::mma_sync(acc[i][j], al[i], bh[j], acc[i][j]);
                }
        }
        __syncthreads();
    }

    // ---- epilogue: stage through smem, then bias/relu + split or scatter ----
    float* stage = (float*)smem;           // 64KB <= TG_SMEM
    float* wst = stage + wid * 2048;
#pragma unroll
    for (int i = 0; i < 4; i++)
#pragma unroll
        for (int j = 0; j < 2; j++)
            wmma::store_matrix_sync(wst + (i * 16) * 32 + j * 16, acc[i][j],
                                    32, wmma::mem_row_major);
    __syncthreads();

#pragma unroll
    for (int it = 0; it < 16; it++) {
        const int idx = tid + it * 256;
        const int r   = idx >> 5;
        const int c4  = idx & 31;
        const int gr  = mb + r;
        if (gr >= m_count) continue;
        const int cc  = c4 * 4;
        const float* sp = stage + (((r >> 6) + ((cc >> 5) << 1)) * 2048)
                        + (r & 63) * 32 + (cc & 31);
        float4 v  = *(const float4*)sp;
        float4 b4 = *(const float4*)(bias + nb + cc);
        v.x += b4.x; v.y += b4.y; v.z += b4.z; v.w += b4.w;
        if (RELU) {
            v.x = fmaxf(v.x, 0.f); v.y = fmaxf(v.y, 0.f);
            v.z = fmaxf(v.z, 0.f); v.w = fmaxf(v.w, 0.f);
        }
        if (OUTMODE == 0) {
            __nv_bfloat16 h0,h1,h2,h3,l0,l1,l2,l3;
            split2(v.x,h0,l0); split2(v.y,h1,l1); split2(v.z,h2,l2); split2(v.w,h3,l3);
            __nv_bfloat162 H0(h0,h1), H1(h2,h3), L0(l0,l1), L1(l2,l3);
            uint2 uh, ul;
            uh.x=*(uint32_t*)&H0; uh.y=*(uint32_t*)&H1;
            ul.x=*(uint32_t*)&L0; ul.y=*(uint32_t*)&L1;
            *(uint2*)(Ch + (size_t)gr * N + nb + cc) = uh;
            *(uint2*)(Cl + (size_t)gr * N + nb + cc) = ul;
        } else {
            const int crow = g_active_tok[gr];
            *(float4*)(Cf + (size_t)crow * N + nb + cc) = v;
        }
    }
}

// ======================= fp32 SGEMM (sel MLP — exact) ======================
template<int AMODE, bool DYNM, bool RELU, bool SCATTER>
__global__ void __launch_bounds__(256, 2)
gemm_kernel(const float* __restrict__ A0, const float* __restrict__ A1,
            const float* __restrict__ W, const float* __restrict__ bias,
            float* __restrict__ C, int M, int K, int N)
{
    __shared__ float As[2][8][128];
    __shared__ float Ws[2][8][128];

    const int m_count = DYNM ? g_count : M;
    const int mb = blockIdx.y * 128;
    if (mb >= m_count) return;
    const int nb = blockIdx.x * 128;

    const int tid  = threadIdx.x;
    const int arow = tid >> 1;
    const int akc  = (tid & 1) << 2;
    const int wkr  = tid >> 5;
    const int wnc  = (tid & 31) << 2;

    const int  gr = mb + arow;
    const bool rv = (!DYNM) || (gr < m_count);

    const float* pa0 = A0 + (size_t)(rv ? gr : 0) * (size_t)K;
    const float* pw = W + (size_t)wkr * N + nb + wnc;

    const int tx = tid & 15;
    const int ty = tid >> 4;

    float acc[8][8];
#pragma unroll
    for (int i = 0; i < 8; i++)
#pragma unroll
        for (int j = 0; j < 8; j++) acc[i][j] = 0.f;

    const int nkt = K >> 3;
    float4 a_reg, w_reg;

    if (!rv) a_reg = make_float4(0.f, 0.f, 0.f, 0.f);
    else     a_reg = *(const float4*)(pa0 + akc);
    w_reg = *(const float4*)(pw);

    As[0][akc + 0][arow] = a_reg.x;
    As[0][akc + 1][arow] = a_reg.y;
    As[0][akc + 2][arow] = a_reg.z;
    As[0][akc + 3][arow] = a_reg.w;
    *(float4*)&Ws[0][wkr][wnc] = w_reg;
    __syncthreads();

    int buf = 0;
    for (int kt = 0; kt < nkt; kt++) {
        const bool more = (kt + 1 < nkt);
        if (more) {
            const int gk = (kt + 1) * 8 + akc;
            a_reg = rv ? *(const float4*)(pa0 + gk) : make_float4(0.f, 0.f, 0.f, 0.f);
            w_reg = *(const float4*)(pw + (size_t)(kt + 1) * 8 * N);
        }
#pragma unroll
        for (int k = 0; k < 8; k++) {
            float4 a0  = *(const float4*)&As[buf][k][ty * 4];
            float4 a1v = *(const float4*)&As[buf][k][64 + ty * 4];
            float4 b0  = *(const float4*)&Ws[buf][k][tx * 4];
            float4 b1v = *(const float4*)&Ws[buf][k][64 + tx * 4];
            float av[8] = {a0.x, a0.y, a0.z, a0.w, a1v.x, a1v.y, a1v.z, a1v.w};
            float bv[8] = {b0.x, b0.y, b0.z, b0.w, b1v.x, b1v.y, b1v.z, b1v.w};
#pragma unroll
            for (int i = 0; i < 8; i++)
#pragma unroll
                for (int j = 0; j < 8; j++)
                    acc[i][j] += av[i] * bv[j];
        }
        if (more) {
            buf ^= 1;
            As[buf][akc + 0][arow] = a_reg.x;
            As[buf][akc + 1][arow] = a_reg.y;
            As[buf][akc + 2][arow] = a_reg.z;
            As[buf][akc + 3][arow] = a_reg.w;
            *(float4*)&Ws[buf][wkr][wnc] = w_reg;
            __syncthreads();
        }
    }

    float4 bs0 = *(const float4*)(bias + nb + tx * 4);
    float4 bs1 = *(const float4*)(bias + nb + 64 + tx * 4);
    float bcol[8] = {bs0.x, bs0.y, bs0.z, bs0.w, bs1.x, bs1.y, bs1.z, bs1.w};

#pragma unroll
    for (int i = 0; i < 8; i++) {
        const int rl = (i < 4) ? (ty * 4 + i) : (64 + ty * 4 + (i - 4));
        const int r  = mb + rl;
        if (DYNM && r >= m_count) continue;
        const int crow = SCATTER ? g_active_tok[r] : r;
        float* cp = C + (size_t)crow * N + nb;
        float v[8];
#pragma unroll
        for (int j = 0; j < 8; j++) {
            float x = acc[i][j] + bcol[j];
            v[j] = RELU ? fmaxf(x, 0.f) : x;
        }
        *(float4*)(cp + tx * 4)      = make_float4(v[0], v[1], v[2], v[3]);
        *(float4*)(cp + 64 + tx * 4) = make_float4(v[4], v[5], v[6], v[7]);
    }
}

// ======================= select (gate/softmax/top3) ========================
__device__ __forceinline__ float warp_sum(float v) {
#pragma unroll
    for (int s = 16; s > 0; s >>= 1) v += __shfl_xor_sync(0xffffffffu, v, s);
    return v;
}
__device__ __forceinline__ float warp_max(float v) {
#pragma unroll
    for (int s = 16; s > 0; s >>= 1) v = fmaxf(v, __shfl_xor_sync(0xffffffffu, v, s));
    return v;
}
__device__ __forceinline__ unsigned long long warp_maxull(unsigned long long v) {
#pragma unroll
    for (int s = 16; s > 0; s >>= 1) {
        unsigned long long o = __shfl_xor_sync(0xffffffffu, v, s);
        v = (o > v) ? o : v;
    }
    return v;
}

__global__ void select_kernel(const float* __restrict__ hidden,
                              const float* __restrict__ gate_w,
                              const float* __restrict__ gate_b,
                              float* __restrict__ out_enh,
                              float* __restrict__ out_probs,
                              float* __restrict__ out_call)
{
    const int t    = blockIdx.x;
    const int tid  = threadIdx.x;
    const int lane = tid & 31;
    const int wrp  = tid >> 5;

    __shared__ float sredf[4];
    __shared__ unsigned long long sredu[4];
    __shared__ float s_gate;
    __shared__ int   s_top[3];
    __shared__ int   s_active;

    const float* hrow = hidden + (size_t)t * 2048;

    float acc = 0.f;
#pragma unroll
    for (int i = 0; i < 16; i++)
        acc += hrow[tid + i * 128] * gate_w[tid + i * 128];
    acc = warp_sum(acc);
    if (lane == 0) sredf[wrp] = acc;
    __syncthreads();
    if (tid == 0) s_gate = sredf[0] + sredf[1] + sredf[2] + sredf[3] + gate_b[0];
    __syncthreads();
    const bool should = s_gate > 0.f;

    const float lg = g_logits[(size_t)t * 128 + tid];
    float m = warp_max(lg);
    if (lane == 0) sredf[wrp] = m;
    __syncthreads();
    const float mx = fmaxf(fmaxf(sredf[0], sredf[1]), fmaxf(sredf[2], sredf[3]));
    const float e = expf(lg - mx);
    float sm = warp_sum(e);
    __syncthreads();
    if (lane == 0) sredf[wrp] = sm;
    __syncthreads();
    const float denom = sredf[0] + sredf[1] + sredf[2] + sredf[3];
    out_probs[(size_t)t * 128 + tid] = e / denom;

    unsigned fb = __float_as_uint(lg);
    fb = (fb & 0x80000000u) ? ~fb : (fb | 0x80000000u);
    unsigned long long key =
        ((unsigned long long)fb << 32) | (unsigned)(127 - tid);

    for (int kk = 0; kk < 3; kk++) {
        unsigned long long k2 = warp_maxull(key);
        if (lane == 0) sredu[wrp] = k2;
        __syncthreads();
        if (tid == 0) {
            unsigned long long best = sredu[0];
            if (sredu[1] > best) best = sredu[1];
            if (sredu[2] > best) best = sredu[2];
            if (sredu[3] > best) best = sredu[3];
            s_top[kk] = 127 - (int)(best & 0xffffffffu);
        }
        __syncthreads();
        if (tid == s_top[kk]) key = 0;
    }

    if (tid == 0) {
        int last = -1, selt = 0;
#pragma unroll
        for (int kk = 0; kk < 3; kk++) {
            if (should && s_top[kk] < 64) { last = kk; selt = s_top[kk]; }
        }
        out_call[t] = should ? 1.f : 0.f;
        if (last >= 0) {
            const int pos = atomicAdd(&g_count, 1);
            g_active_tok[pos]  = t;
            g_active_tool[pos] = selt;
            s_active = 1;
        } else {
            s_active = 0;
        }
    }
    __syncthreads();

    if (!s_active) {
        const float4* hv = (const float4*)hrow;
        float4* ov = (float4*)(out_enh + (size_t)t * 2048);
#pragma unroll
        for (int i = 0; i < 4; i++)
            ov[tid + i * 128] = hv[tid + i * 128];
    }
}

// ===========================================================================
extern "C" void kernel_launch(void* const* d_in, const int* in_sizes, int n_in,
                              void* d_out, int out_size)
{
    if (n_in < 16) return;
    const float* hidden = (const float*)d_in[0];
    const float* emb    = (const float*)d_in[1];
    const float* gate_w = (const float*)d_in[2];
    const float* gate_b = (const float*)d_in[3];
    const float* sel_w1 = (const float*)d_in[4];
    const float* sel_b1 = (const float*)d_in[5];
    const float* sel_w2 = (const float*)d_in[6];
    const float* sel_b2 = (const float*)d_in[7];
    const float* pg_w1  = (const float*)d_in[8];
    const float* pg_b1  = (const float*)d_in[9];
    const float* pg_w2  = (const float*)d_in[10];
    const float* pg_b2  = (const float*)d_in[11];
    const float* ri_w1  = (const float*)d_in[12];
    const float* ri_b1  = (const float*)d_in[13];
    const float* ri_w2  = (const float*)d_in[14];
    const float* ri_b2  = (const float*)d_in[15];

    const int Ntok = in_sizes[0] / 2048;
    float* out       = (float*)d_out;
    float* out_enh   = out;
    float* out_probs = out + (size_t)Ntok * 2048;
    float* out_call  = out_probs + (size_t)Ntok * 128;

    float *p_h1, *p_logits;
    cudaGetSymbolAddress((void**)&p_h1,     g_h1);
    cudaGetSymbolAddress((void**)&p_logits, g_logits);
    __nv_bfloat16 *p_whi, *p_wlo, *p_hh, *p_hl, *p_eh, *p_el;
    __nv_bfloat16 *p_p1h, *p_p1l, *p_trh, *p_trl, *p_r1h, *p_r1l;
    cudaGetSymbolAddress((void**)&p_whi, g_whi);
    cudaGetSymbolAddress((void**)&p_wlo, g_wlo);
    cudaGetSymbolAddress((void**)&p_hh,  g_hh);
    cudaGetSymbolAddress((void**)&p_hl,  g_hl);
    cudaGetSymbolAddress((void**)&p_eh,  g_eh);
    cudaGetSymbolAddress((void**)&p_el,  g_el);
    cudaGetSymbolAddress((void**)&p_p1h, g_p1h);
    cudaGetSymbolAddress((void**)&p_p1l, g_p1l);
    cudaGetSymbolAddress((void**)&p_trh, g_trh);
    cudaGetSymbolAddress((void**)&p_trl, g_trl);
    cudaGetSymbolAddress((void**)&p_r1h, g_r1h);
    cudaGetSymbolAddress((void**)&p_r1l, g_r1l);

    cudaFuncSetAttribute(tgemm_kernel<1, true,  0>, cudaFuncAttributeMaxDynamicSharedMemorySize, TG_SMEM);
    cudaFuncSetAttribute(tgemm_kernel<0, false, 0>, cudaFuncAttributeMaxDynamicSharedMemorySize, TG_SMEM);
    cudaFuncSetAttribute(tgemm_kernel<2, true,  0>, cudaFuncAttributeMaxDynamicSharedMemorySize, TG_SMEM);
    cudaFuncSetAttribute(tgemm_kernel<0, false, 1>, cudaFuncAttributeMaxDynamicSharedMemorySize, TG_SMEM);

    const int MB = (Ntok + 127) / 128;

    reset_kernel<<<1, 1>>>();

    // weight split+transpose (bf16 hi/lo, [N,K]) for pg/ri
    wsplit_kernel<<<dim3(512/32, 2304/32), dim3(32,8)>>>(pg_w1, p_whi + WS_PG1, p_wlo + WS_PG1, 2304, 512);
    wsplit_kernel<<<dim3(2048/32, 512/32), dim3(32,8)>>>(pg_w2, p_whi + WS_PG2, p_wlo + WS_PG2, 512, 2048);
    wsplit_kernel<<<dim3(512/32, 4096/32), dim3(32,8)>>>(ri_w1, p_whi + WS_RI1, p_wlo + WS_RI1, 4096, 512);
    wsplit_kernel<<<dim3(2048/32, 512/32), dim3(32,8)>>>(ri_w2, p_whi + WS_RI2, p_wlo + WS_RI2, 512, 2048);

    // activation pre-split: hidden + emb
    const int hid4 = Ntok * 2048 / 4;
    fsplit_kernel<<<(hid4 + 255) / 256, 256>>>(hidden, p_hh, p_hl, hid4);
    fsplit_kernel<<<(128 * 256 / 4 + 255) / 256, 256>>>(emb, p_eh, p_el, 128 * 256 / 4);

    // selector MLP (all tokens, exact fp32)
    gemm_kernel<0, false, true,  false><<<dim3(4,  MB), 256>>>(hidden, nullptr, sel_w1, sel_b1, p_h1,     Ntok, 2048, 512);
    gemm_kernel<0, false, false, false><<<dim3(1,  MB), 256>>>(p_h1,   nullptr, sel_w2, sel_b2, p_logits, Ntok, 512,  128);

    // gate + softmax + top3 + compaction + passthrough
    select_kernel<<<Ntok, 128>>>(hidden, gate_w, gate_b, out_enh, out_probs, out_call);

    // param generator (active tokens)
    tgemm_kernel<1, true,  0><<<dim3(4,  MB), 256, TG_SMEM>>>(p_hh, p_hl, p_eh, p_el,
        p_whi + WS_PG1, p_wlo + WS_PG1, pg_b1, nullptr, p_p1h, p_p1l, 2304, 512);
    tgemm_kernel<0, false, 0><<<dim3(16, MB), 256, TG_SMEM>>>(p_p1h, p_p1l, nullptr, nullptr,
        p_whi + WS_PG2, p_wlo + WS_PG2, pg_b2, nullptr, p_trh, p_trl, 512, 2048);

    // result integration (active tokens); final scatter to enhanced (fp32)
    tgemm_kernel<2, true,  0><<<dim3(4,  MB), 256, TG_SMEM>>>(p_hh, p_hl, p_trh, p_trl,
        p_whi + WS_RI1, p_wlo + WS_RI1, ri_b1, nullptr, p_r1h, p_r1l, 4096, 512);
    tgemm_kernel<0, false, 1><<<dim3(16, MB), 256, TG_SMEM>>>(p_r1h, p_r1l, nullptr, nullptr,
        p_whi + WS_RI2, p_wlo + WS_RI2, ri_b2, out_enh, nullptr, nullptr, 512, 2048);
}